// round 2
// baseline (speedup 1.0000x reference)
#include <cuda_runtime.h>

// Deformable Conv3d, fp32.
// prep: x -> channels-last xT[b][spatial][c]; weight -> wT[k][c][o].
// deform: block = 32 points x 64 outs. Per k:
//   sample s[k+1] (warp gathers, coalesced 256B channel vectors) into
//   double-buffered shared tile, then GEMM k with lane=point mapping:
//   per 4c: 1x LDS.128 s + 8x broadcast float4 w -> 32 FFMA/lane.

namespace {
constexpr int B_    = 2;
constexpr int CIN_  = 64;
constexpr int COUT_ = 64;
constexpr int D_    = 8;
constexpr int H_    = 32;
constexpr int W_    = 32;
constexpr int K_    = 27;
constexpr int P_    = D_ * H_ * W_;   // 8192
constexpr int TP    = 32;             // points per block
constexpr int THREADS = 256;
constexpr int SPITCH = 68;            // floats per sS row (conflict-free, 16B-mult)
}

__device__ float g_xT[B_ * P_ * CIN_];       // [b][spatial][c]
__device__ float g_wT[K_ * CIN_ * COUT_];    // [k][c][o]

__global__ void prep_kernel(const float* __restrict__ x,
                            const float* __restrict__ w) {
    int stride = gridDim.x * blockDim.x;
    int tid = blockIdx.x * blockDim.x + threadIdx.x;
    for (int i = tid; i < B_ * CIN_ * P_; i += stride) {
        int s = i % P_;
        int c = (i / P_) % CIN_;
        int b = i / (P_ * CIN_);
        g_xT[(b * P_ + s) * CIN_ + c] = x[i];
    }
    for (int i = tid; i < COUT_ * CIN_ * K_; i += stride) {
        int k = i % K_;
        int c = (i / K_) % CIN_;
        int o = i / (K_ * CIN_);
        g_wT[(k * CIN_ + c) * COUT_ + o] = w[i];
    }
}

__global__ __launch_bounds__(THREADS)
void deform_kernel(const float* __restrict__ offset,
                   const float* __restrict__ bias,
                   float* __restrict__ out) {
    __shared__ float sS[2][TP][SPITCH];  // double-buffered sampled tile
    __shared__ float sW[CIN_ * COUT_];   // [c][o] for current k

    const int tid  = threadIdx.x;
    const int lane = tid & 31;
    const int warp = tid >> 5;           // 8 warps
    const int blk  = blockIdx.x;
    const int b    = blk >> 8;
    const int p0   = (blk & 255) * TP;

    const float* offB = offset + (size_t)b * 3 * K_ * P_;
    const float* xTb  = g_xT   + (size_t)b * P_ * CIN_;

    const int plb = warp * 4;            // this warp samples points plb..plb+3
    const int o0  = warp * 8;            // this warp's GEMM output slice

    int od[4], oh[4], ow[4], pg[4];
#pragma unroll
    for (int i = 0; i < 4; i++) {
        int p = p0 + plb + i;
        pg[i] = p;
        od[i] = p >> 10;
        oh[i] = (p >> 5) & 31;
        ow[i] = p & 31;
    }

    const int half = lane >> 4;          // corner half
    const int c4   = lane & 15;          // float4 channel chunk

    float acc[8];
#pragma unroll
    for (int j = 0; j < 8; j++) acc[j] = 0.f;

    // ---- sampling of tap k into buffer `buf` ----
    auto sample_k = [&](int k, int buf) {
        const int kd = k / 9, kh = (k / 3) % 3, kw = k % 3;
#pragma unroll
        for (int i = 0; i < 4; i++) {
            const int p = pg[i];
            float zd = (float)(od[i] - 1 + kd) + __ldg(&offB[(3 * k + 0) * P_ + p]);
            float zh = (float)(oh[i] - 1 + kh) + __ldg(&offB[(3 * k + 1) * P_ + p]);
            float zw = (float)(ow[i] - 1 + kw) + __ldg(&offB[(3 * k + 2) * P_ + p]);
            float fd = floorf(zd), fh = floorf(zh), fw = floorf(zw);
            int d0 = (int)fd, h0 = (int)fh, w0 = (int)fw;
            float rd = zd - fd, rh = zh - fh, rw = zw - fw;

            float4 a = make_float4(0.f, 0.f, 0.f, 0.f);
#pragma unroll
            for (int jj = 0; jj < 4; jj++) {
                int j  = jj * 2 + half;
                int dd = (j >> 2) & 1, dh = (j >> 1) & 1, dw = j & 1;
                int di = d0 + dd, hi = h0 + dh, wi = w0 + dw;
                bool valid = (di >= 0) & (di < D_) & (hi >= 0) & (hi < H_) &
                             (wi >= 0) & (wi < W_);
                float wgt = (dd ? rd : 1.f - rd) * (dh ? rh : 1.f - rh) *
                            (dw ? rw : 1.f - rw);
                wgt = valid ? wgt : 0.f;
                int dic = min(max(di, 0), D_ - 1);
                int hic = min(max(hi, 0), H_ - 1);
                int wic = min(max(wi, 0), W_ - 1);
                int idx = (dic * H_ + hic) * W_ + wic;
                float4 v = *reinterpret_cast<const float4*>(xTb + idx * CIN_ + c4 * 4);
                a.x += wgt * v.x; a.y += wgt * v.y;
                a.z += wgt * v.z; a.w += wgt * v.w;
            }
            a.x += __shfl_down_sync(0xffffffffu, a.x, 16);
            a.y += __shfl_down_sync(0xffffffffu, a.y, 16);
            a.z += __shfl_down_sync(0xffffffffu, a.z, 16);
            a.w += __shfl_down_sync(0xffffffffu, a.w, 16);
            if (half == 0)
                *reinterpret_cast<float4*>(&sS[buf][plb + i][c4 * 4]) = a;
        }
    };

    auto stage_w = [&](int k) {
        const float4* wsrc = reinterpret_cast<const float4*>(g_wT + k * CIN_ * COUT_);
        float4* wdst = reinterpret_cast<float4*>(sW);
        for (int i = tid; i < (CIN_ * COUT_) / 4; i += THREADS)
            wdst[i] = wsrc[i];
    };

    // prologue
    stage_w(0);
    sample_k(0, 0);
    __syncthreads();

    for (int k = 0; k < K_; k++) {
        const int buf = k & 1;

        // issue next tap's gathers first (overlaps GEMM across warps)
        if (k + 1 < K_) sample_k(k + 1, buf ^ 1);

        // ---- GEMM: lane = point, 8 output channels per warp ----
#pragma unroll
        for (int c = 0; c < CIN_; c += 4) {
            float4 s = *reinterpret_cast<const float4*>(&sS[buf][lane][c]);
            float sv[4] = {s.x, s.y, s.z, s.w};
#pragma unroll
            for (int j = 0; j < 4; j++) {
                float4 w0 = *reinterpret_cast<const float4*>(&sW[(c + j) * COUT_ + o0]);
                float4 w1 = *reinterpret_cast<const float4*>(&sW[(c + j) * COUT_ + o0 + 4]);
                acc[0] += sv[j] * w0.x; acc[1] += sv[j] * w0.y;
                acc[2] += sv[j] * w0.z; acc[3] += sv[j] * w0.w;
                acc[4] += sv[j] * w1.x; acc[5] += sv[j] * w1.y;
                acc[6] += sv[j] * w1.z; acc[7] += sv[j] * w1.w;
            }
        }
        __syncthreads();              // GEMM[k] done: sW free, sS[buf] free
        if (k + 1 < K_) {
            stage_w(k + 1);
            __syncthreads();          // sW[k+1] + sS[buf^1] ready
        }
    }

    const int p = p0 + lane;
#pragma unroll
    for (int j = 0; j < 8; j++)
        out[((size_t)b * COUT_ + o0 + j) * P_ + p] = acc[j] + bias[o0 + j];
}

extern "C" void kernel_launch(void* const* d_in, const int* in_sizes, int n_in,
                              void* d_out, int out_size) {
    const float* x      = (const float*)d_in[0];
    const float* offset = (const float*)d_in[1];
    const float* weight = (const float*)d_in[2];
    const float* bias   = (const float*)d_in[3];
    float* out = (float*)d_out;

    prep_kernel<<<256, THREADS>>>(x, weight);
    deform_kernel<<<B_ * (P_ / TP), THREADS>>>(offset, bias, out);
}